// round 16
// baseline (speedup 1.0000x reference)
#include <cuda_runtime.h>
#include <cuda_fp16.h>
#include <cstdint>

#define BN   32
#define SEQ  577
#define CH   768
#define NH   12
#define DH   64
#define MROWS (BN*SEQ)      /* 18464 */
#define QKV_N (3*CH)        /* 2304  */
#define QT   128
#define KT   128
#define NKT  5              /* ceil(577/128) */

// q scale: DH^-0.5 * log2(e)  (softmax runs in exp2 domain)
#define QSCALE 0.180336879f
#define SOFT_OFF 12.0f      /* fixed softmax offset (exp2 domain) */

// ---------------- scratch (__device__ globals; no allocs allowed) ----------
__device__ __half g_qh[BN*NH*SEQ*DH];                        // q fp16 (scaled)
__device__ __half g_kh[BN*NH*SEQ*DH];                        // k fp16
__device__ __half g_vh[BN*NH*SEQ*DH];                        // v fp16
__device__ __half g_xh[MROWS*CH];                            // A fp16 (x, then attn out)
__device__ __half g_wh[QKV_N*CH];                            // qkv_w fp16
__device__ __half g_ph[CH*CH];                               // proj_w fp16

// ---------------- helpers ---------------------------------------------------
__device__ __forceinline__ uint32_t smem_u32(const void* p) {
    uint32_t a;
    asm("{ .reg .u64 t; cvta.to.shared.u64 t, %1; cvt.u32.u64 %0, t; }" : "=r"(a) : "l"(p));
    return a;
}
__device__ __forceinline__ void cpa16(uint32_t dst, const void* src) {
    asm volatile("cp.async.cg.shared.global [%0], [%1], 16;" :: "r"(dst), "l"(src) : "memory");
}
#define CP_COMMIT() asm volatile("cp.async.commit_group;" ::: "memory")
#define CP_WAIT0()  asm volatile("cp.async.wait_group 0;" ::: "memory")
#define CP_WAIT1()  asm volatile("cp.async.wait_group 1;" ::: "memory")
#define CP_WAIT2()  asm volatile("cp.async.wait_group 2;" ::: "memory")

__device__ __forceinline__ void ldsm_x4(uint32_t& r0, uint32_t& r1,
                                        uint32_t& r2, uint32_t& r3, uint32_t addr) {
    asm volatile("ldmatrix.sync.aligned.m8n8.x4.shared.b16 {%0,%1,%2,%3}, [%4];"
                 : "=r"(r0), "=r"(r1), "=r"(r2), "=r"(r3) : "r"(addr));
}
__device__ __forceinline__ void ldsm_x4_t(uint32_t& r0, uint32_t& r1,
                                          uint32_t& r2, uint32_t& r3, uint32_t addr) {
    asm volatile("ldmatrix.sync.aligned.m8n8.x4.trans.shared.b16 {%0,%1,%2,%3}, [%4];"
                 : "=r"(r0), "=r"(r1), "=r"(r2), "=r"(r3) : "r"(addr));
}
__device__ __forceinline__ void mma16816(float* c, const uint32_t* a, const uint32_t* b) {
    asm volatile("mma.sync.aligned.m16n8k16.row.col.f32.f16.f16.f32 "
                 "{%0,%1,%2,%3}, {%4,%5,%6,%7}, {%8,%9}, {%0,%1,%2,%3};"
                 : "+f"(c[0]), "+f"(c[1]), "+f"(c[2]), "+f"(c[3])
                 : "r"(a[0]), "r"(a[1]), "r"(a[2]), "r"(a[3]), "r"(b[0]), "r"(b[1]));
}
__device__ __forceinline__ void mma2(float* c, const uint32_t* a, uint32_t b0, uint32_t b1) {
    asm volatile("mma.sync.aligned.m16n8k16.row.col.f32.f16.f16.f32 "
                 "{%0,%1,%2,%3}, {%4,%5,%6,%7}, {%8,%9}, {%0,%1,%2,%3};"
                 : "+f"(c[0]), "+f"(c[1]), "+f"(c[2]), "+f"(c[3])
                 : "r"(a[0]), "r"(a[1]), "r"(a[2]), "r"(a[3]), "r"(b0), "r"(b1));
}
// GEMM tile swizzle: 64B rows, 4 chunks
__device__ __forceinline__ uint32_t swoff(int r, int c) {
    return (uint32_t)(r * 64 + ((c ^ ((r >> 1) & 3)) << 4));
}
// attention tile swizzle: 128B rows, 8 chunks
__device__ __forceinline__ uint32_t aswz(int r, int c) {
    return (uint32_t)(r * 128 + ((c ^ (r & 7)) << 4));
}
__device__ __forceinline__ uint32_t pack2h(float x, float y) {
    __half2 h2 = __floats2half2_rn(x, y);
    return reinterpret_cast<uint32_t&>(h2);
}

// ---------------- fused vectorized fp32 -> fp16 convert ---------------------
#define N0_4 (MROWS*CH/4)
#define N1_4 (QKV_N*CH/4)
#define N2_4 (CH*CH/4)
__global__ void convert_all(const float* __restrict__ x,
                            const float* __restrict__ w,
                            const float* __restrict__ p) {
    int i = blockIdx.x * 256 + threadIdx.x;
    const float4* src; __half* dst; int j;
    if (i < N0_4)                 { src = (const float4*)x; dst = g_xh; j = i; }
    else if (i < N0_4 + N1_4)     { src = (const float4*)w; dst = g_wh; j = i - N0_4; }
    else if (i < N0_4+N1_4+N2_4)  { src = (const float4*)p; dst = g_ph; j = i - N0_4 - N1_4; }
    else return;
    float4 v = src[j];
    uint2 o;
    o.x = pack2h(v.x, v.y);
    o.y = pack2h(v.z, v.w);
    *(uint2*)(dst + (size_t)j * 4) = o;
}

// ---------------- mma.sync fp16 GEMM, 4-stage cp.async ----------------------
// CTA 128x128, BK=32, 128 thr / 4 warps (2x2 grid of 64x64 warp tiles),
// 4-stage cp.async (64KB dynamic smem), ONE __syncthreads per chunk, 2 CTA/SM.
#define G_STG 16384
#define G_SMEM (4 * G_STG)

template<int MODE>
__global__ __launch_bounds__(128, 2) void mma_gemm(const float* __restrict__ bias,
                                                   float* __restrict__ out)
{
    extern __shared__ __align__(16) char smem[];
    const uint32_t sb = smem_u32(smem);
    const int tid = threadIdx.x, lane = tid & 31, wid = tid >> 5;
    const int wm = wid & 1, wn = wid >> 1;
    const int tileN = blockIdx.x, tileM = blockIdx.y;

    const __half* __restrict__ Ah = g_xh;
    const __half* __restrict__ Bh = (MODE == 0) ? g_wh : g_ph;

    const uint32_t OFF_AH = 0, OFF_BH = 8192;

    uint32_t lso[4]; size_t la[4], lb[4];
    #pragma unroll
    for (int i = 0; i < 4; ++i) {
        int slot = tid + (i << 7);
        int r = slot >> 2, c = slot & 3;
        lso[i] = swoff(r, c);
        int ga = tileM * 128 + r; if (ga > MROWS - 1) ga = MROWS - 1;
        la[i] = (size_t)ga * CH + c * 8;
        lb[i] = (size_t)(tileN * 128 + r) * CH + c * 8;
    }

    float acc[4][8][4];
    #pragma unroll
    for (int i = 0; i < 4; ++i)
        #pragma unroll
        for (int j = 0; j < 8; ++j)
            #pragma unroll
            for (int r = 0; r < 4; ++r) acc[i][j][r] = 0.f;

    // prologue: chunks 0..2 into stages 0..2
    #pragma unroll
    for (int pc = 0; pc < 3; ++pc) {
        const uint32_t st = sb + pc * G_STG;
        const size_t ko = (size_t)pc * 32;
        #pragma unroll
        for (int i = 0; i < 4; ++i) {
            cpa16(st + OFF_AH + lso[i], Ah + la[i] + ko);
            cpa16(st + OFF_BH + lso[i], Bh + lb[i] + ko);
        }
        CP_COMMIT();
    }

    for (int kc = 0; kc < 24; ++kc) {
        if (kc <= 21)      { CP_WAIT2(); }
        else if (kc == 22) { CP_WAIT1(); }
        else               { CP_WAIT0(); }
        __syncthreads();
        if (kc + 3 < 24) {                 // issue chunk kc+3 into stage (kc+3)%4
            const uint32_t st = sb + ((kc + 3) & 3) * G_STG;
            const size_t ko = (size_t)(kc + 3) * 32;
            #pragma unroll
            for (int i = 0; i < 4; ++i) {
                cpa16(st + OFF_AH + lso[i], Ah + la[i] + ko);
                cpa16(st + OFF_BH + lso[i], Bh + lb[i] + ko);
            }
            CP_COMMIT();
        }

        const uint32_t st = sb + (kc & 3) * G_STG;
        #pragma unroll
        for (int k16 = 0; k16 < 2; ++k16) {
            uint32_t ah[4][4];
            #pragma unroll
            for (int mf = 0; mf < 4; ++mf) {
                int row = wm * 64 + mf * 16 + (lane & 15);
                int c   = 2 * k16 + (lane >> 4);
                uint32_t o = swoff(row, c);
                ldsm_x4(ah[mf][0], ah[mf][1], ah[mf][2], ah[mf][3], st + OFF_AH + o);
            }
            uint32_t bh[8][2];
            #pragma unroll
            for (int np = 0; np < 4; ++np) {
                int g = lane >> 3, l = lane & 7;
                int row = wn * 64 + np * 16 + (g >> 1) * 8 + l;
                int c   = 2 * k16 + (g & 1);
                uint32_t o = swoff(row, c);
                ldsm_x4(bh[np*2][0], bh[np*2][1], bh[np*2+1][0], bh[np*2+1][1],
                        st + OFF_BH + o);
            }
            #pragma unroll
            for (int mf = 0; mf < 4; ++mf)
                #pragma unroll
                for (int nf = 0; nf < 8; ++nf)
                    mma16816(acc[mf][nf], ah[mf], bh[nf]);
        }
    }

    // ---------------- epilogue ----------------
    const int s = (MODE == 0) ? (tileN * 128) / CH : 0;
    const float scl = (MODE == 0 && s == 0) ? QSCALE : 1.0f;

    #pragma unroll
    for (int mf = 0; mf < 4; ++mf) {
        const int rbase = tileM * 128 + wm * 64 + mf * 16 + (lane >> 2);
        #pragma unroll
        for (int nf = 0; nf < 8; ++nf) {
            const int gcol = tileN * 128 + wn * 64 + nf * 8 + ((lane & 3) << 1);
            const float b0 = bias[gcol], b1 = bias[gcol + 1];
            #pragma unroll
            for (int hh = 0; hh < 2; ++hh) {
                const int row = rbase + hh * 8;
                if (row >= MROWS) continue;
                float v0 = (acc[mf][nf][hh*2+0] + b0) * scl;
                float v1 = (acc[mf][nf][hh*2+1] + b1) * scl;
                if (MODE == 0) {
                    int rem = gcol - s * CH;
                    int hd = rem >> 6, d = rem & 63;
                    int bb = row / SEQ, n = row - bb * SEQ;
                    size_t di = ((size_t)(bb * NH + hd) * SEQ + n) * DH + d;
                    __half* dst = (s == 0) ? g_qh : (s == 1) ? g_kh : g_vh;
                    *(uint32_t*)(dst + di) = pack2h(v0, v1);
                } else {
                    *(float2*)(out + (size_t)row * CH + gcol) = make_float2(v0, v1);
                }
            }
        }
    }
}

// ---------------- mma.sync flash attention, fixed-offset softmax ------------
// smem 64KB: [0:16K) QH / stage1-KH, [16K:48K) stage0 (KH,VH),
//            [48K:64K) stage1-VH.
#define ATT_SMEM 65536

__global__ __launch_bounds__(256) void attn_mma()
{
    extern __shared__ char sm[];
    const uint32_t sb = smem_u32(sm);
    const int tid = threadIdx.x, lane = tid & 31, w = tid >> 5;
    const int q0 = blockIdx.x * QT;
    const int hh = blockIdx.y, b = blockIdx.z;
    const size_t hb = (size_t)(b * NH + hh) * SEQ;

    int lr4[4], lc4[4]; uint32_t lso[4];
    #pragma unroll
    for (int p = 0; p < 4; ++p) {
        int slot = tid + (p << 8);
        lr4[p] = slot >> 3;
        lc4[p] = (slot & 7) * 8;
        lso[p] = aswz(slot >> 3, slot & 7);
    }

    // prologue: Q + KV tile 0 via cp.async
    #pragma unroll
    for (int p = 0; p < 4; ++p) {
        int gr = q0 + lr4[p]; if (gr > SEQ - 1) gr = SEQ - 1;
        size_t qi = ((hb + gr) << 6) + lc4[p];
        cpa16(sb + 0 + lso[p], g_qh + qi);
        int gk = lr4[p]; if (gk > SEQ - 1) gk = SEQ - 1;
        size_t ki = ((hb + gk) << 6) + lc4[p];
        cpa16(sb + 16384 + lso[p], g_kh + ki);
        cpa16(sb + 32768 + lso[p], g_vh + ki);
    }
    CP_COMMIT();
    CP_WAIT0();
    __syncthreads();

    uint32_t qh[4][4];
    #pragma unroll
    for (int kd = 0; kd < 4; ++kd) {
        int row = w * 16 + (lane & 15);
        int c = 2 * kd + (lane >> 4);
        uint32_t o = aswz(row, c);
        ldsm_x4(qh[kd][0], qh[kd][1], qh[kd][2], qh[kd][3], sb + 0 + o);
    }
    __syncthreads();

    float o[8][4];
    #pragma unroll
    for (int i = 0; i < 8; ++i)
        #pragma unroll
        for (int j = 0; j < 4; ++j) o[i][j] = 0.f;
    float l0 = 0.f, l1 = 0.f;        // lane-local; reduced once at the end

    for (int kt = 0; kt < NKT; ++kt) {
        if (kt + 1 < NKT) {
            const uint32_t nKH = ((kt + 1) & 1) ? (sb + 0u)     : (sb + 16384u);
            const uint32_t nVH = ((kt + 1) & 1) ? (sb + 49152u) : (sb + 32768u);
            const int k0n = (kt + 1) * KT;
            #pragma unroll
            for (int p = 0; p < 4; ++p) {
                int gk = k0n + lr4[p]; if (gk > SEQ - 1) gk = SEQ - 1;
                size_t ki = ((hb + gk) << 6) + lc4[p];
                cpa16(nKH + lso[p], g_kh + ki);
                cpa16(nVH + lso[p], g_vh + ki);
            }
            CP_COMMIT();
        }

        const uint32_t sKH = (kt & 1) ? (sb + 0u)     : (sb + 16384u);
        const uint32_t sVH = (kt & 1) ? (sb + 49152u) : (sb + 32768u);
        const int k0 = kt * KT;

        float s[16][4];
        #pragma unroll
        for (int i = 0; i < 16; ++i)
            #pragma unroll
            for (int j = 0; j < 4; ++j) s[i][j] = 0.f;

        #pragma unroll
        for (int kp = 0; kp < 8; ++kp) {
            #pragma unroll
            for (int kd = 0; kd < 4; ++kd) {
                int g = lane >> 3, li = lane & 7;
                int row = kp * 16 + ((g >> 1) << 3) + li;
                int c = 2 * kd + (g & 1);
                uint32_t so = aswz(row, c);
                uint32_t kh4[4];
                ldsm_x4(kh4[0], kh4[1], kh4[2], kh4[3], sKH + so);
                mma2(s[2*kp],   qh[kd], kh4[0], kh4[1]);
                mma2(s[2*kp+1], qh[kd], kh4[2], kh4[3]);
            }
        }

        if (k0 + KT > SEQ) {
            #pragma unroll
            for (int kn = 0; kn < 16; ++kn) {
                int kg = k0 + kn * 8 + ((lane & 3) << 1);
                if (kg >= SEQ)     { s[kn][0] = -1e30f; s[kn][2] = -1e30f; }
                if (kg + 1 >= SEQ) { s[kn][1] = -1e30f; s[kn][3] = -1e30f; }
            }
        }

        // ---- fixed-offset softmax: P = exp2(s - SOFT_OFF) ----
        float sum0 = 0.f, sum1 = 0.f;
        #pragma unroll
        for (int kn = 0; kn < 16; ++kn) {
            s[kn][0] = exp2f(s[kn][0] - SOFT_OFF);
            s[kn][1] = exp2f(s[kn][1] - SOFT_OFF);
            s[kn][2] = exp2f(s[kn][2] - SOFT_OFF);
            s[kn][3] = exp2f(s[kn][3] - SOFT_OFF);
            sum0 += s[kn][0] + s[kn][1];
            sum1 += s[kn][2] + s[kn][3];
        }
        l0 += sum0; l1 += sum1;

        #pragma unroll
        for (int kk = 0; kk < 8; ++kk) {
            uint32_t ph[4];
            ph[0] = pack2h(s[2*kk][0],   s[2*kk][1]);
            ph[1] = pack2h(s[2*kk][2],   s[2*kk][3]);
            ph[2] = pack2h(s[2*kk+1][0], s[2*kk+1][1]);
            ph[3] = pack2h(s[2*kk+1][2], s[2*kk+1][3]);
            #pragma unroll
            for (int d16 = 0; d16 < 4; ++d16) {
                int g = lane >> 3, li = lane & 7;
                int row = kk * 16 + ((g & 1) << 3) + li;
                int c = d16 * 2 + (g >> 1);
                uint32_t so = aswz(row, c);
                uint32_t vh4[4];
                ldsm_x4_t(vh4[0], vh4[1], vh4[2], vh4[3], sVH + so);
                mma2(o[2*d16],   ph, vh4[0], vh4[1]);
                mma2(o[2*d16+1], ph, vh4[2], vh4[3]);
            }
        }

        if (kt + 1 < NKT) {
            CP_WAIT0();
            __syncthreads();
        }
    }

    // deferred l reduction across the 4 lanes of each row-quad
    l0 += __shfl_xor_sync(0xffffffffu, l0, 1);
    l0 += __shfl_xor_sync(0xffffffffu, l0, 2);
    l1 += __shfl_xor_sync(0xffffffffu, l1, 1);
    l1 += __shfl_xor_sync(0xffffffffu, l1, 2);

    // ---- epilogue: o/l -> fp16 into proj-A buffer ----
    float r0 = 1.f / l0, r1 = 1.f / l1;
    int rg = lane >> 2, t2 = (lane & 3) << 1;
    int row0 = q0 + w * 16 + rg, row1 = row0 + 8;
    #pragma unroll
    for (int nf = 0; nf < 8; ++nf) {
        int col = hh * DH + nf * 8 + t2;
        if (row0 < SEQ) {
            size_t gi = (size_t)(b * SEQ + row0) * CH + col;
            *(uint32_t*)(g_xh + gi) = pack2h(o[nf][0] * r0, o[nf][1] * r0);
        }
        if (row1 < SEQ) {
            size_t gi = (size_t)(b * SEQ + row1) * CH + col;
            *(uint32_t*)(g_xh + gi) = pack2h(o[nf][2] * r1, o[nf][3] * r1);
        }
    }
}

// ---------------------------------------------------------------------------
extern "C" void kernel_launch(void* const* d_in, const int* in_sizes, int n_in,
                              void* d_out, int out_size)
{
    const float* x      = (const float*)d_in[0];
    const float* qkv_w  = (const float*)d_in[1];
    const float* qkv_b  = (const float*)d_in[2];
    const float* proj_w = (const float*)d_in[3];
    const float* proj_b = (const float*)d_in[4];
    float* out = (float*)d_out;

    cudaFuncSetAttribute(mma_gemm<0>, cudaFuncAttributeMaxDynamicSharedMemorySize, G_SMEM);
    cudaFuncSetAttribute(mma_gemm<1>, cudaFuncAttributeMaxDynamicSharedMemorySize, G_SMEM);
    cudaFuncSetAttribute(attn_mma, cudaFuncAttributeMaxDynamicSharedMemorySize, ATT_SMEM);

    const int NTOT4 = N0_4 + N1_4 + N2_4;
    convert_all<<<(NTOT4 + 255)/256, 256>>>(x, qkv_w, proj_w);

    mma_gemm<0><<<dim3(QKV_N/128, (MROWS + 127)/128), 128, G_SMEM>>>(qkv_b, nullptr);

    attn_mma<<<dim3((SEQ + QT - 1)/QT, NH, BN), 256, ATT_SMEM>>>();

    mma_gemm<1><<<dim3(CH/128, (MROWS + 127)/128), 128, G_SMEM>>>(proj_b, out);
}

// round 17
// speedup vs baseline: 1.0074x; 1.0074x over previous
#include <cuda_runtime.h>
#include <cuda_fp16.h>
#include <cstdint>

#define BN   32
#define SEQ  577
#define CH   768
#define NH   12
#define DH   64
#define MROWS (BN*SEQ)      /* 18464 */
#define QKV_N (3*CH)        /* 2304  */
#define QT   128
#define KT   128
#define NKT  5              /* ceil(577/128) */

// q scale: DH^-0.5 * log2(e)  (softmax runs in exp2 domain)
#define QSCALE 0.180336879f
#define SOFT_OFF 12.0f      /* fixed softmax offset (exp2 domain) */

// ---------------- scratch (__device__ globals; no allocs allowed) ----------
__device__ __half g_qh[BN*NH*SEQ*DH];                        // q fp16 (scaled)
__device__ __half g_kh[BN*NH*SEQ*DH];                        // k fp16
__device__ __half g_vh[BN*NH*SEQ*DH];                        // v fp16
__device__ __half g_xh[MROWS*CH];                            // A fp16 (x, then attn out)
__device__ __half g_wh[QKV_N*CH];                            // qkv_w fp16
__device__ __half g_ph[CH*CH];                               // proj_w fp16

// ---------------- helpers ---------------------------------------------------
__device__ __forceinline__ uint32_t smem_u32(const void* p) {
    uint32_t a;
    asm("{ .reg .u64 t; cvta.to.shared.u64 t, %1; cvt.u32.u64 %0, t; }" : "=r"(a) : "l"(p));
    return a;
}
__device__ __forceinline__ void cpa16(uint32_t dst, const void* src) {
    asm volatile("cp.async.cg.shared.global [%0], [%1], 16;" :: "r"(dst), "l"(src) : "memory");
}
#define CP_COMMIT() asm volatile("cp.async.commit_group;" ::: "memory")
#define CP_WAIT0()  asm volatile("cp.async.wait_group 0;" ::: "memory")
#define CP_WAIT1()  asm volatile("cp.async.wait_group 1;" ::: "memory")

__device__ __forceinline__ void ldsm_x4(uint32_t& r0, uint32_t& r1,
                                        uint32_t& r2, uint32_t& r3, uint32_t addr) {
    asm volatile("ldmatrix.sync.aligned.m8n8.x4.shared.b16 {%0,%1,%2,%3}, [%4];"
                 : "=r"(r0), "=r"(r1), "=r"(r2), "=r"(r3) : "r"(addr));
}
__device__ __forceinline__ void ldsm_x4_t(uint32_t& r0, uint32_t& r1,
                                          uint32_t& r2, uint32_t& r3, uint32_t addr) {
    asm volatile("ldmatrix.sync.aligned.m8n8.x4.trans.shared.b16 {%0,%1,%2,%3}, [%4];"
                 : "=r"(r0), "=r"(r1), "=r"(r2), "=r"(r3) : "r"(addr));
}
__device__ __forceinline__ void mma16816(float* c, const uint32_t* a, const uint32_t* b) {
    asm volatile("mma.sync.aligned.m16n8k16.row.col.f32.f16.f16.f32 "
                 "{%0,%1,%2,%3}, {%4,%5,%6,%7}, {%8,%9}, {%0,%1,%2,%3};"
                 : "+f"(c[0]), "+f"(c[1]), "+f"(c[2]), "+f"(c[3])
                 : "r"(a[0]), "r"(a[1]), "r"(a[2]), "r"(a[3]), "r"(b[0]), "r"(b[1]));
}
__device__ __forceinline__ void mma2(float* c, const uint32_t* a, uint32_t b0, uint32_t b1) {
    asm volatile("mma.sync.aligned.m16n8k16.row.col.f32.f16.f16.f32 "
                 "{%0,%1,%2,%3}, {%4,%5,%6,%7}, {%8,%9}, {%0,%1,%2,%3};"
                 : "+f"(c[0]), "+f"(c[1]), "+f"(c[2]), "+f"(c[3])
                 : "r"(a[0]), "r"(a[1]), "r"(a[2]), "r"(a[3]), "r"(b0), "r"(b1));
}
// GEMM tile swizzle: 64B rows, 4 chunks
__device__ __forceinline__ uint32_t swoff(int r, int c) {
    return (uint32_t)(r * 64 + ((c ^ ((r >> 1) & 3)) << 4));
}
// attention tile swizzle: 128B rows, 8 chunks
__device__ __forceinline__ uint32_t aswz(int r, int c) {
    return (uint32_t)(r * 128 + ((c ^ (r & 7)) << 4));
}
__device__ __forceinline__ uint32_t pack2h(float x, float y) {
    __half2 h2 = __floats2half2_rn(x, y);
    return reinterpret_cast<uint32_t&>(h2);
}

// ---------------- fused vectorized fp32 -> fp16 convert ---------------------
#define N0_4 (MROWS*CH/4)
#define N1_4 (QKV_N*CH/4)
#define N2_4 (CH*CH/4)
__global__ void convert_all(const float* __restrict__ x,
                            const float* __restrict__ w,
                            const float* __restrict__ p) {
    int i = blockIdx.x * 256 + threadIdx.x;
    const float4* src; __half* dst; int j;
    if (i < N0_4)                 { src = (const float4*)x; dst = g_xh; j = i; }
    else if (i < N0_4 + N1_4)     { src = (const float4*)w; dst = g_wh; j = i - N0_4; }
    else if (i < N0_4+N1_4+N2_4)  { src = (const float4*)p; dst = g_ph; j = i - N0_4 - N1_4; }
    else return;
    float4 v = src[j];
    uint2 o;
    o.x = pack2h(v.x, v.y);
    o.y = pack2h(v.z, v.w);
    *(uint2*)(dst + (size_t)j * 4) = o;
}

// ---------------- mma.sync fp16 GEMM, 3-stage cp.async (R15 proven) ---------
// CTA 128x128, BK=32, 128 thr / 4 warps (2x2 grid of 64x64 warp tiles),
// 3-stage cp.async (48KB static smem), ONE __syncthreads per chunk, 2 CTA/SM.
#define G_STG 16384

template<int MODE>
__global__ __launch_bounds__(128, 2) void mma_gemm(const float* __restrict__ bias,
                                                   float* __restrict__ out)
{
    __shared__ __align__(16) char smem[3 * G_STG];   // 48KB static
    const uint32_t sb = smem_u32(smem);
    const int tid = threadIdx.x, lane = tid & 31, wid = tid >> 5;
    const int wm = wid & 1, wn = wid >> 1;
    const int tileN = blockIdx.x, tileM = blockIdx.y;

    const __half* __restrict__ Ah = g_xh;
    const __half* __restrict__ Bh = (MODE == 0) ? g_wh : g_ph;

    const uint32_t OFF_AH = 0, OFF_BH = 8192;

    uint32_t lso[4]; size_t la[4], lb[4];
    #pragma unroll
    for (int i = 0; i < 4; ++i) {
        int slot = tid + (i << 7);
        int r = slot >> 2, c = slot & 3;
        lso[i] = swoff(r, c);
        int ga = tileM * 128 + r; if (ga > MROWS - 1) ga = MROWS - 1;
        la[i] = (size_t)ga * CH + c * 8;
        lb[i] = (size_t)(tileN * 128 + r) * CH + c * 8;
    }

    float acc[4][8][4];
    #pragma unroll
    for (int i = 0; i < 4; ++i)
        #pragma unroll
        for (int j = 0; j < 8; ++j)
            #pragma unroll
            for (int r = 0; r < 4; ++r) acc[i][j][r] = 0.f;

    // prologue: chunks 0,1 into stages 0,1
    #pragma unroll
    for (int pc = 0; pc < 2; ++pc) {
        const uint32_t st = sb + pc * G_STG;
        const size_t ko = (size_t)pc * 32;
        #pragma unroll
        for (int i = 0; i < 4; ++i) {
            cpa16(st + OFF_AH + lso[i], Ah + la[i] + ko);
            cpa16(st + OFF_BH + lso[i], Bh + lb[i] + ko);
        }
        CP_COMMIT();
    }

    for (int kc = 0; kc < 24; ++kc) {
        if (kc < 23) { CP_WAIT1(); } else { CP_WAIT0(); }   // chunk kc landed
        __syncthreads();
        if (kc + 2 < 24) {                 // issue chunk kc+2 into stage (kc+2)%3
            const uint32_t st = sb + ((kc + 2) % 3) * G_STG;
            const size_t ko = (size_t)(kc + 2) * 32;
            #pragma unroll
            for (int i = 0; i < 4; ++i) {
                cpa16(st + OFF_AH + lso[i], Ah + la[i] + ko);
                cpa16(st + OFF_BH + lso[i], Bh + lb[i] + ko);
            }
            CP_COMMIT();
        }

        const uint32_t st = sb + (kc % 3) * G_STG;
        #pragma unroll
        for (int k16 = 0; k16 < 2; ++k16) {
            uint32_t ah[4][4];
            #pragma unroll
            for (int mf = 0; mf < 4; ++mf) {
                int row = wm * 64 + mf * 16 + (lane & 15);
                int c   = 2 * k16 + (lane >> 4);
                uint32_t o = swoff(row, c);
                ldsm_x4(ah[mf][0], ah[mf][1], ah[mf][2], ah[mf][3], st + OFF_AH + o);
            }
            uint32_t bh[8][2];
            #pragma unroll
            for (int np = 0; np < 4; ++np) {
                int g = lane >> 3, l = lane & 7;
                int row = wn * 64 + np * 16 + (g >> 1) * 8 + l;
                int c   = 2 * k16 + (g & 1);
                uint32_t o = swoff(row, c);
                ldsm_x4(bh[np*2][0], bh[np*2][1], bh[np*2+1][0], bh[np*2+1][1],
                        st + OFF_BH + o);
            }
            #pragma unroll
            for (int mf = 0; mf < 4; ++mf)
                #pragma unroll
                for (int nf = 0; nf < 8; ++nf)
                    mma16816(acc[mf][nf], ah[mf], bh[nf]);
        }
    }

    // ---------------- epilogue ----------------
    const int s = (MODE == 0) ? (tileN * 128) / CH : 0;
    const float scl = (MODE == 0 && s == 0) ? QSCALE : 1.0f;

    #pragma unroll
    for (int mf = 0; mf < 4; ++mf) {
        const int rbase = tileM * 128 + wm * 64 + mf * 16 + (lane >> 2);
        #pragma unroll
        for (int nf = 0; nf < 8; ++nf) {
            const int gcol = tileN * 128 + wn * 64 + nf * 8 + ((lane & 3) << 1);
            const float b0 = bias[gcol], b1 = bias[gcol + 1];
            #pragma unroll
            for (int hh = 0; hh < 2; ++hh) {
                const int row = rbase + hh * 8;
                if (row >= MROWS) continue;
                float v0 = (acc[mf][nf][hh*2+0] + b0) * scl;
                float v1 = (acc[mf][nf][hh*2+1] + b1) * scl;
                if (MODE == 0) {
                    int rem = gcol - s * CH;
                    int hd = rem >> 6, d = rem & 63;
                    int bb = row / SEQ, n = row - bb * SEQ;
                    size_t di = ((size_t)(bb * NH + hd) * SEQ + n) * DH + d;
                    __half* dst = (s == 0) ? g_qh : (s == 1) ? g_kh : g_vh;
                    *(uint32_t*)(dst + di) = pack2h(v0, v1);
                } else {
                    *(float2*)(out + (size_t)row * CH + gcol) = make_float2(v0, v1);
                }
            }
        }
    }
}

// ---------------- mma.sync flash attention, fixed-offset softmax ------------
// smem 64KB: [0:16K) QH / stage1-KH, [16K:48K) stage0 (KH,VH),
//            [48K:64K) stage1-VH.
#define ATT_SMEM 65536

__global__ __launch_bounds__(256) void attn_mma()
{
    extern __shared__ char sm[];
    const uint32_t sb = smem_u32(sm);
    const int tid = threadIdx.x, lane = tid & 31, w = tid >> 5;
    const int q0 = blockIdx.x * QT;
    const int hh = blockIdx.y, b = blockIdx.z;
    const size_t hb = (size_t)(b * NH + hh) * SEQ;

    int lr4[4], lc4[4]; uint32_t lso[4];
    #pragma unroll
    for (int p = 0; p < 4; ++p) {
        int slot = tid + (p << 8);
        lr4[p] = slot >> 3;
        lc4[p] = (slot & 7) * 8;
        lso[p] = aswz(slot >> 3, slot & 7);
    }

    // prologue: Q + KV tile 0 via cp.async
    #pragma unroll
    for (int p = 0; p < 4; ++p) {
        int gr = q0 + lr4[p]; if (gr > SEQ - 1) gr = SEQ - 1;
        size_t qi = ((hb + gr) << 6) + lc4[p];
        cpa16(sb + 0 + lso[p], g_qh + qi);
        int gk = lr4[p]; if (gk > SEQ - 1) gk = SEQ - 1;
        size_t ki = ((hb + gk) << 6) + lc4[p];
        cpa16(sb + 16384 + lso[p], g_kh + ki);
        cpa16(sb + 32768 + lso[p], g_vh + ki);
    }
    CP_COMMIT();
    CP_WAIT0();
    __syncthreads();

    uint32_t qh[4][4];
    #pragma unroll
    for (int kd = 0; kd < 4; ++kd) {
        int row = w * 16 + (lane & 15);
        int c = 2 * kd + (lane >> 4);
        uint32_t o = aswz(row, c);
        ldsm_x4(qh[kd][0], qh[kd][1], qh[kd][2], qh[kd][3], sb + 0 + o);
    }
    __syncthreads();

    float o[8][4];
    #pragma unroll
    for (int i = 0; i < 8; ++i)
        #pragma unroll
        for (int j = 0; j < 4; ++j) o[i][j] = 0.f;
    float l0 = 0.f, l1 = 0.f;        // lane-local; reduced once at the end

    for (int kt = 0; kt < NKT; ++kt) {
        if (kt + 1 < NKT) {
            const uint32_t nKH = ((kt + 1) & 1) ? (sb + 0u)     : (sb + 16384u);
            const uint32_t nVH = ((kt + 1) & 1) ? (sb + 49152u) : (sb + 32768u);
            const int k0n = (kt + 1) * KT;
            #pragma unroll
            for (int p = 0; p < 4; ++p) {
                int gk = k0n + lr4[p]; if (gk > SEQ - 1) gk = SEQ - 1;
                size_t ki = ((hb + gk) << 6) + lc4[p];
                cpa16(nKH + lso[p], g_kh + ki);
                cpa16(nVH + lso[p], g_vh + ki);
            }
            CP_COMMIT();
        }

        const uint32_t sKH = (kt & 1) ? (sb + 0u)     : (sb + 16384u);
        const uint32_t sVH = (kt & 1) ? (sb + 49152u) : (sb + 32768u);
        const int k0 = kt * KT;

        float s[16][4];
        #pragma unroll
        for (int i = 0; i < 16; ++i)
            #pragma unroll
            for (int j = 0; j < 4; ++j) s[i][j] = 0.f;

        #pragma unroll
        for (int kp = 0; kp < 8; ++kp) {
            #pragma unroll
            for (int kd = 0; kd < 4; ++kd) {
                int g = lane >> 3, li = lane & 7;
                int row = kp * 16 + ((g >> 1) << 3) + li;
                int c = 2 * kd + (g & 1);
                uint32_t so = aswz(row, c);
                uint32_t kh4[4];
                ldsm_x4(kh4[0], kh4[1], kh4[2], kh4[3], sKH + so);
                mma2(s[2*kp],   qh[kd], kh4[0], kh4[1]);
                mma2(s[2*kp+1], qh[kd], kh4[2], kh4[3]);
            }
        }

        if (k0 + KT > SEQ) {
            #pragma unroll
            for (int kn = 0; kn < 16; ++kn) {
                int kg = k0 + kn * 8 + ((lane & 3) << 1);
                if (kg >= SEQ)     { s[kn][0] = -1e30f; s[kn][2] = -1e30f; }
                if (kg + 1 >= SEQ) { s[kn][1] = -1e30f; s[kn][3] = -1e30f; }
            }
        }

        // ---- fixed-offset softmax: P = exp2(s - SOFT_OFF) ----
        float sum0 = 0.f, sum1 = 0.f;
        #pragma unroll
        for (int kn = 0; kn < 16; ++kn) {
            s[kn][0] = exp2f(s[kn][0] - SOFT_OFF);
            s[kn][1] = exp2f(s[kn][1] - SOFT_OFF);
            s[kn][2] = exp2f(s[kn][2] - SOFT_OFF);
            s[kn][3] = exp2f(s[kn][3] - SOFT_OFF);
            sum0 += s[kn][0] + s[kn][1];
            sum1 += s[kn][2] + s[kn][3];
        }
        l0 += sum0; l1 += sum1;

        #pragma unroll
        for (int kk = 0; kk < 8; ++kk) {
            uint32_t ph[4];
            ph[0] = pack2h(s[2*kk][0],   s[2*kk][1]);
            ph[1] = pack2h(s[2*kk][2],   s[2*kk][3]);
            ph[2] = pack2h(s[2*kk+1][0], s[2*kk+1][1]);
            ph[3] = pack2h(s[2*kk+1][2], s[2*kk+1][3]);
            #pragma unroll
            for (int d16 = 0; d16 < 4; ++d16) {
                int g = lane >> 3, li = lane & 7;
                int row = kk * 16 + ((g & 1) << 3) + li;
                int c = d16 * 2 + (g >> 1);
                uint32_t so = aswz(row, c);
                uint32_t vh4[4];
                ldsm_x4_t(vh4[0], vh4[1], vh4[2], vh4[3], sVH + so);
                mma2(o[2*d16],   ph, vh4[0], vh4[1]);
                mma2(o[2*d16+1], ph, vh4[2], vh4[3]);
            }
        }

        if (kt + 1 < NKT) {
            CP_WAIT0();
            __syncthreads();
        }
    }

    // deferred l reduction across the 4 lanes of each row-quad
    l0 += __shfl_xor_sync(0xffffffffu, l0, 1);
    l0 += __shfl_xor_sync(0xffffffffu, l0, 2);
    l1 += __shfl_xor_sync(0xffffffffu, l1, 1);
    l1 += __shfl_xor_sync(0xffffffffu, l1, 2);

    // ---- epilogue: o/l -> fp16 into proj-A buffer ----
    float r0 = 1.f / l0, r1 = 1.f / l1;
    int rg = lane >> 2, t2 = (lane & 3) << 1;
    int row0 = q0 + w * 16 + rg, row1 = row0 + 8;
    #pragma unroll
    for (int nf = 0; nf < 8; ++nf) {
        int col = hh * DH + nf * 8 + t2;
        if (row0 < SEQ) {
            size_t gi = (size_t)(b * SEQ + row0) * CH + col;
            *(uint32_t*)(g_xh + gi) = pack2h(o[nf][0] * r0, o[nf][1] * r0);
        }
        if (row1 < SEQ) {
            size_t gi = (size_t)(b * SEQ + row1) * CH + col;
            *(uint32_t*)(g_xh + gi) = pack2h(o[nf][2] * r1, o[nf][3] * r1);
        }
    }
}

// ---------------------------------------------------------------------------
extern "C" void kernel_launch(void* const* d_in, const int* in_sizes, int n_in,
                              void* d_out, int out_size)
{
    const float* x      = (const float*)d_in[0];
    const float* qkv_w  = (const float*)d_in[1];
    const float* qkv_b  = (const float*)d_in[2];
    const float* proj_w = (const float*)d_in[3];
    const float* proj_b = (const float*)d_in[4];
    float* out = (float*)d_out;

    cudaFuncSetAttribute(attn_mma, cudaFuncAttributeMaxDynamicSharedMemorySize, ATT_SMEM);

    const int NTOT4 = N0_4 + N1_4 + N2_4;
    convert_all<<<(NTOT4 + 255)/256, 256>>>(x, qkv_w, proj_w);

    mma_gemm<0><<<dim3(QKV_N/128, (MROWS + 127)/128), 128>>>(qkv_b, nullptr);

    attn_mma<<<dim3((SEQ + QT - 1)/QT, NH, BN), 256, ATT_SMEM>>>();

    mma_gemm<1><<<dim3(CH/128, (MROWS + 127)/128), 128>>>(proj_b, out);
}